// round 1
// baseline (speedup 1.0000x reference)
#include <cuda_runtime.h>
#include <math.h>

#define NPTS 2048
#define NB   8
#define BN   (NPTS*NB)
#define DD   16
#define HH   64
#define KSEL 32
#define CAND_MAX 128
#define STEPS 2

static __device__ __align__(16) float  g_A[BN*HH];      // A[i][h] = b1 + x_i . W1[:16]
static __device__ __align__(16) float  g_B[BN*HH];      // B[j][h] = x_j . W1[16:]
static __device__ __align__(16) float2 g_pos[BN];
static __device__ __align__(16) float  g_grad[BN*DD];
static __device__ __align__(16) float  g_xbuf[BN*DD];
static __device__ __align__(16) float  g_UVt[HH*32];    // [h][0:16]=W1a[d][h]*w[h], [h][16:32]=W1b[d][h]*w[h]
static __device__                float g_su[32];        // rowsums of U (0:16) and V (16:32)

__global__ void prep_kernel(const float* __restrict__ W1,
                            const float* __restrict__ W2,
                            const float* __restrict__ Wout) {
    int h = threadIdx.x;  // 64 threads
    float wv = 0.f;
    #pragma unroll
    for (int c = 0; c < 32; c++) wv = fmaf(W2[h*32 + c], Wout[c], wv);
    #pragma unroll
    for (int d = 0; d < 16; d++) {
        g_UVt[h*32 + d]      = W1[d*64 + h]      * wv;
        g_UVt[h*32 + 16 + d] = W1[(16+d)*64 + h] * wv;
    }
    __syncthreads();
    if (h < 32) {
        float s = 0.f;
        for (int hh = 0; hh < 64; hh++) s += g_UVt[hh*32 + h];
        g_su[h] = s;
    }
}

__global__ void featurize_kernel(const float* __restrict__ xin,
                                 const float* __restrict__ W1,
                                 const float* __restrict__ b1,
                                 int use_buf) {
    const float* xs = use_buf ? g_xbuf : xin;
    int g = threadIdx.x >> 6;
    int h = threadIdx.x & 63;
    int p = blockIdx.x * 4 + g;
    __shared__ float sx[4][16];
    if (h < 16) sx[g][h] = xs[p*DD + h];
    __syncthreads();
    float a = b1[h], bb = 0.f;
    #pragma unroll
    for (int d = 0; d < 16; d++) {
        float xv = sx[g][d];
        a  = fmaf(xv, W1[d*64 + h],      a);
        bb = fmaf(xv, W1[(16+d)*64 + h], bb);
    }
    g_A[(size_t)p*64 + h] = a;
    g_B[(size_t)p*64 + h] = bb;
    if (h < 16) g_grad[p*16 + h] = 0.f;
    if (h == 0) g_pos[p] = make_float2(sx[g][0], sx[g][1]);
}

__global__ void __launch_bounds__(256) edges_kernel() {
    __shared__ __align__(16) float2 s_pos[NPTS];      // 16 KB
    __shared__ __align__(16) float  s_UVt[HH*32];     // 8 KB
    __shared__ float s_su[32];
    __shared__ __align__(16) float s_Ai[8][64];       // 2 KB
    __shared__ float s_cd2[8][CAND_MAX];              // 4 KB
    __shared__ int   s_cj[8][CAND_MAX];               // 4 KB
    __shared__ int   s_sel[8][KSEL];                  // 1 KB

    const float R2 = 0.08f * 0.08f;
    int tid  = threadIdx.x;
    int lane = tid & 31;
    int w    = tid >> 5;
    int batch = blockIdx.x >> 8;      // 256 blocks per batch (2048 pts / 8 pts per block)
    int grp   = blockIdx.x & 255;
    int base  = batch * NPTS;

    for (int t = tid; t < NPTS; t += 256) s_pos[t] = g_pos[base + t];
    for (int t = tid; t < HH*32; t += 256) s_UVt[t] = g_UVt[t];
    if (tid < 32) s_su[tid] = g_su[tid];
    __syncthreads();

    int il = grp * 8 + w;             // local point index within batch
    int ig = base + il;               // global point index
    float2 pi = s_pos[il];

    // stage A[i] row for this warp
    s_Ai[w][lane]      = g_A[(size_t)ig*64 + lane];
    s_Ai[w][32 + lane] = g_A[(size_t)ig*64 + 32 + lane];

    // ---- candidate scan: all j with d2 < R2 (excl. self) ----
    int cnt = 0;
    unsigned lt = (1u << lane) - 1u;
    for (int k = 0; k < NPTS/32; k++) {
        int j = k*32 + lane;
        float2 pj = s_pos[j];
        float dx = pj.x - pi.x, dy = pj.y - pi.y;
        float d2 = fmaf(dx, dx, dy*dy);
        bool ok = (d2 < R2) && (j != il);
        unsigned m = __ballot_sync(0xffffffffu, ok);
        if (ok) {
            int p = cnt + __popc(m & lt);
            if (p < CAND_MAX) { s_cd2[w][p] = d2; s_cj[w][p] = j; }
        }
        cnt += __popc(m);
    }
    int M = min(cnt, CAND_MAX);
    __syncwarp();

    // ---- select 32 smallest (rank addressing; ties broken by index) ----
    int S;
    if (M <= KSEL) {
        if (lane < M) s_sel[w][lane] = s_cj[w][lane];
        S = M;
    } else {
        for (int c = lane; c < M; c += 32) {
            float dc = s_cd2[w][c];
            int   jc = s_cj[w][c];
            int rank = 0;
            for (int t = 0; t < M; t++) {
                float dt_ = s_cd2[w][t];
                rank += (int)((dt_ < dc) || ((dt_ == dc) && (s_cj[w][t] < jc)));
            }
            if (rank < KSEL) s_sel[w][rank] = jc;
        }
        S = KSEL;
    }
    __syncwarp();

    // ---- edge compute: one lane per edge ----
    if (lane < S) {
        int jl = s_sel[w][lane];
        int jg = base + jl;
        const float4* Bj4 = reinterpret_cast<const float4*>(g_B + (size_t)jg*64);
        const float4* Ai4 = reinterpret_cast<const float4*>(&s_Ai[w][0]);
        float gx[16], gj[16];
        #pragma unroll
        for (int d = 0; d < 16; d++) { gx[d] = 0.f; gj[d] = 0.f; }

        #pragma unroll 1
        for (int h4 = 0; h4 < 16; h4++) {
            float4 b4 = __ldg(Bj4 + h4);
            float4 a4 = Ai4[h4];
            float ss[4];
            {
                float t0 = tanhf(a4.x + b4.x);
                float t1 = tanhf(a4.y + b4.y);
                float t2 = tanhf(a4.z + b4.z);
                float t3 = tanhf(a4.w + b4.w);
                ss[0] = t0*t0; ss[1] = t1*t1; ss[2] = t2*t2; ss[3] = t3*t3;
            }
            #pragma unroll
            for (int q = 0; q < 4; q++) {
                const float* UV = s_UVt + (h4*4 + q) * 32;  // uniform addr -> broadcast LDS.128
                float sq = ss[q];
                #pragma unroll
                for (int d = 0; d < 16; d++) {
                    gx[d] = fmaf(UV[d],      sq, gx[d]);
                    gj[d] = fmaf(UV[16 + d], sq, gj[d]);
                }
            }
        }
        // grad contribution: su[d] - sum_h U[d][h]*t^2  (g = (1-t^2)*w folded into U/V)
        float* gip = g_grad + (size_t)ig*16;
        float* gjp = g_grad + (size_t)jg*16;
        #pragma unroll
        for (int d = 0; d < 16; d++) {
            atomicAdd(gip + d, s_su[d]      - gx[d]);
            atomicAdd(gjp + d, s_su[16 + d] - gj[d]);
        }
    }
}

__global__ void update_kernel(const float* __restrict__ xin,
                              float* __restrict__ out, int use_buf) {
    int i = blockIdx.x * 256 + threadIdx.x;
    const float* xs = use_buf ? g_xbuf : xin;
    float v = xs[i] - 0.01f * g_grad[i];
    g_xbuf[i] = v;
    out[i] = v;
}

extern "C" void kernel_launch(void* const* d_in, const int* in_sizes, int n_in,
                              void* d_out, int out_size) {
    (void)in_sizes; (void)n_in; (void)out_size;
    const float* x    = (const float*)d_in[0];
    const float* W1   = (const float*)d_in[1];
    const float* b1   = (const float*)d_in[2];
    const float* W2   = (const float*)d_in[3];
    const float* Wout = (const float*)d_in[5];
    float* out = (float*)d_out;

    prep_kernel<<<1, 64>>>(W1, W2, Wout);
    for (int s = 0; s < STEPS; s++) {
        featurize_kernel<<<BN/4, 256>>>(x, W1, b1, s > 0);
        edges_kernel<<<BN/8, 256>>>();
        update_kernel<<<(BN*DD)/256, 256>>>(x, out, s > 0);
    }
}

// round 2
// speedup vs baseline: 1.4093x; 1.4093x over previous
#include <cuda_runtime.h>
#include <math.h>

#define NPTS 2048
#define NB   8
#define BN   (NPTS*NB)
#define DD   16
#define HH   64
#define KSEL 32
#define CAND_MAX 128
#define WPB  8

static __device__ __align__(16) float  g_A[BN*HH];
static __device__ __align__(16) float  g_B[BN*HH];
static __device__ __align__(16) float2 g_pos[BN];
static __device__ __align__(16) float  g_grad[BN*DD];
static __device__ __align__(16) float  g_xbuf[BN*DD];
static __device__ __align__(16) float  g_UVt[HH*32];   // [h][0:16]=U (W1a*w), [h][16:32]=V (W1b*w)
static __device__                float g_su[32];

__device__ __forceinline__ float tanhax(float x) {
    float y; asm("tanh.approx.f32 %0, %1;" : "=f"(y) : "f"(x)); return y;
}
__device__ __forceinline__ void red_add_v4(float* p, float a, float b, float c, float d) {
    asm volatile("red.global.add.v4.f32 [%0], {%1,%2,%3,%4};"
                 :: "l"(p), "f"(a), "f"(b), "f"(c), "f"(d) : "memory");
}

__global__ void prep_kernel(const float* __restrict__ W1,
                            const float* __restrict__ W2,
                            const float* __restrict__ Wout) {
    int h = threadIdx.x;  // 64 threads
    float wv = 0.f;
    #pragma unroll
    for (int c = 0; c < 32; c++) wv = fmaf(W2[h*32 + c], Wout[c], wv);
    #pragma unroll
    for (int d = 0; d < 16; d++) {
        g_UVt[h*32 + d]      = W1[d*64 + h]      * wv;
        g_UVt[h*32 + 16 + d] = W1[(16+d)*64 + h] * wv;
    }
    __syncthreads();
    if (h < 32) {
        float s = 0.f;
        for (int hh = 0; hh < 64; hh++) s += g_UVt[hh*32 + h];
        g_su[h] = s;
    }
}

// fused: x_new = x - scale*grad ; write out + xbuf ; zero grad ; compute A/B rows ; stash pos
__global__ void __launch_bounds__(512) updfeat_kernel(const float* __restrict__ xin,
                                                      const float* __restrict__ W1,
                                                      const float* __restrict__ b1,
                                                      float* __restrict__ out,
                                                      float scale, int use_buf) {
    int g = threadIdx.x >> 6;
    int h = threadIdx.x & 63;
    int p = blockIdx.x * 8 + g;
    __shared__ float sx[8][16];
    const float* xs = use_buf ? g_xbuf : xin;
    if (h < 16) {
        float v = xs[p*DD + h] - scale * g_grad[p*DD + h];
        sx[g][h] = v;
        g_xbuf[p*DD + h] = v;
        out[p*DD + h]    = v;
        g_grad[p*DD + h] = 0.f;
    }
    __syncthreads();
    float a = b1[h], bb = 0.f;
    #pragma unroll
    for (int d = 0; d < 16; d++) {
        float xv = sx[g][d];
        a  = fmaf(xv, W1[d*64 + h],      a);
        bb = fmaf(xv, W1[(16+d)*64 + h], bb);
    }
    g_A[(size_t)p*64 + h] = a;
    g_B[(size_t)p*64 + h] = bb;
    if (h == 0) g_pos[p] = make_float2(sx[g][0], sx[g][1]);
}

__global__ void __launch_bounds__(256) edges_kernel() {
    __shared__ __align__(16) float2 s_pos[NPTS];        // 16 KB
    __shared__ __align__(16) float  s_UVt[HH*32];       // 8 KB
    __shared__ float s_su[32];
    __shared__ __align__(16) float s_Ai[WPB][64];       // 2 KB
    __shared__ float s_cd2[WPB][CAND_MAX];              // 4 KB
    __shared__ int   s_cj[WPB][CAND_MAX];               // 4 KB
    __shared__ int   s_sel[WPB][KSEL];                  // 1 KB

    const float R2 = 0.08f * 0.08f;
    int tid  = threadIdx.x;
    int lane = tid & 31;
    int w    = tid >> 5;
    int batch = blockIdx.x >> 8;       // 256 blocks per batch
    int grp   = blockIdx.x & 255;
    int base  = batch * NPTS;

    for (int t = tid; t < NPTS; t += 256) s_pos[t] = g_pos[base + t];
    for (int t = tid; t < HH*32; t += 256) s_UVt[t] = g_UVt[t];
    if (tid < 32) s_su[tid] = g_su[tid];
    __syncthreads();

    int il = grp * WPB + w;
    int ig = base + il;
    float2 pi = s_pos[il];

    s_Ai[w][lane]      = g_A[(size_t)ig*64 + lane];
    s_Ai[w][32 + lane] = g_A[(size_t)ig*64 + 32 + lane];

    // ---- candidate scan ----
    int cnt = 0;
    unsigned lt = (1u << lane) - 1u;
    for (int k = 0; k < NPTS/32; k++) {
        int j = k*32 + lane;
        float2 pj = s_pos[j];
        float dx = pj.x - pi.x, dy = pj.y - pi.y;
        float d2 = fmaf(dx, dx, dy*dy);
        bool ok = (d2 < R2) && (j != il);
        unsigned m = __ballot_sync(0xffffffffu, ok);
        if (ok) {
            int p = cnt + __popc(m & lt);
            if (p < CAND_MAX) { s_cd2[w][p] = d2; s_cj[w][p] = j; }
        }
        cnt += __popc(m);
    }
    int M = min(cnt, CAND_MAX);
    __syncwarp();

    // ---- select K smallest (rank, tie by index) ----
    int S;
    if (M <= KSEL) {
        if (lane < M) s_sel[w][lane] = s_cj[w][lane];
        S = M;
    } else {
        for (int c = lane; c < M; c += 32) {
            float dc = s_cd2[w][c];
            int   jc = s_cj[w][c];
            int rank = 0;
            for (int t = 0; t < M; t++) {
                float dt_ = s_cd2[w][t];
                rank += (int)((dt_ < dc) || ((dt_ == dc) && (s_cj[w][t] < jc)));
            }
            if (rank < KSEL) s_sel[w][rank] = jc;
        }
        S = KSEL;
    }
    __syncwarp();

    // ---- edge compute: one lane per edge ----
    float gx[16], gj[16];
    #pragma unroll
    for (int d = 0; d < 16; d++) { gx[d] = 0.f; gj[d] = 0.f; }

    int jg = base;  // dummy
    if (lane < S) {
        int jl = s_sel[w][lane];
        jg = base + jl;
        const float4* Bj4 = reinterpret_cast<const float4*>(g_B + (size_t)jg*64);
        const float4* Ai4 = reinterpret_cast<const float4*>(&s_Ai[w][0]);

        #pragma unroll 4
        for (int h4 = 0; h4 < 16; h4++) {
            float4 b4 = __ldg(Bj4 + h4);
            float4 a4 = Ai4[h4];
            float t0 = tanhax(a4.x + b4.x);
            float t1 = tanhax(a4.y + b4.y);
            float t2 = tanhax(a4.z + b4.z);
            float t3 = tanhax(a4.w + b4.w);
            float ss[4] = { t0*t0, t1*t1, t2*t2, t3*t3 };
            #pragma unroll
            for (int q = 0; q < 4; q++) {
                const float* UV = s_UVt + (h4*4 + q) * 32;  // uniform -> broadcast LDS
                float sq = ss[q];
                #pragma unroll
                for (int d = 0; d < 16; d++) {
                    gx[d] = fmaf(UV[d],      sq, gx[d]);
                    gj[d] = fmaf(UV[16 + d], sq, gj[d]);
                }
            }
        }
        // scatter to neighbor j: contribution = su_V - gj, vectorized red
        float* gjp = g_grad + (size_t)jg*16;
        red_add_v4(gjp + 0,  s_su[16] - gj[0],  s_su[17] - gj[1],  s_su[18] - gj[2],  s_su[19] - gj[3]);
        red_add_v4(gjp + 4,  s_su[20] - gj[4],  s_su[21] - gj[5],  s_su[22] - gj[6],  s_su[23] - gj[7]);
        red_add_v4(gjp + 8,  s_su[24] - gj[8],  s_su[25] - gj[9],  s_su[26] - gj[10], s_su[27] - gj[11]);
        red_add_v4(gjp + 12, s_su[28] - gj[12], s_su[29] - gj[13], s_su[30] - gj[14], s_su[31] - gj[15]);
    }

    // ---- warp-reduce gi (point i exclusive to this warp; inactive lanes hold 0) ----
    #pragma unroll
    for (int d = 0; d < 16; d++) {
        float v = gx[d];
        v += __shfl_xor_sync(0xffffffffu, v, 16);
        v += __shfl_xor_sync(0xffffffffu, v, 8);
        v += __shfl_xor_sync(0xffffffffu, v, 4);
        v += __shfl_xor_sync(0xffffffffu, v, 2);
        v += __shfl_xor_sync(0xffffffffu, v, 1);
        gx[d] = v;
    }
    if (lane < 4) {
        int d0 = lane * 4;
        float fs = (float)S;
        red_add_v4(g_grad + (size_t)ig*16 + d0,
                   fs*s_su[d0+0] - gx[d0+0],
                   fs*s_su[d0+1] - gx[d0+1],
                   fs*s_su[d0+2] - gx[d0+2],
                   fs*s_su[d0+3] - gx[d0+3]);
    }
}

extern "C" void kernel_launch(void* const* d_in, const int* in_sizes, int n_in,
                              void* d_out, int out_size) {
    (void)in_sizes; (void)n_in; (void)out_size;
    const float* x    = (const float*)d_in[0];
    const float* W1   = (const float*)d_in[1];
    const float* b1   = (const float*)d_in[2];
    const float* W2   = (const float*)d_in[3];
    const float* Wout = (const float*)d_in[5];
    float* out = (float*)d_out;

    prep_kernel<<<1, 64>>>(W1, W2, Wout);
    // step 0 featurize (scale=0 -> x unchanged), grad zeroed
    updfeat_kernel<<<BN/8, 512>>>(x, W1, b1, out, 0.0f, 0);
    edges_kernel<<<BN/WPB, 256>>>();
    // step 1 update + featurize
    updfeat_kernel<<<BN/8, 512>>>(x, W1, b1, out, 0.01f, 1);
    edges_kernel<<<BN/WPB, 256>>>();
    // step 2 final update (featurize redundant but harmless)
    updfeat_kernel<<<BN/8, 512>>>(x, W1, b1, out, 0.01f, 1);
}